// round 9
// baseline (speedup 1.0000x reference)
#include <cuda_runtime.h>
#include <stdint.h>

// Pre-emphasis IIR y[i] = x[i] + 0.85*y[i-1]; out[o] = float(clip_int16(32768*y[o+91])),
// out[N-91..] = 0.
// R9: R8's register-only warp-scan, but latency-fixed: dual-window ILP per loop
// iteration (independent Kogge-Stone scans), reg cap 32 -> 64, 3 shuffles/window
// realign. Coalesced LDG.128/STG.128 only (~32 L1 wavefronts per 512 samples).

namespace {
constexpr int   kBlock = 256;
constexpr int   kWin   = 128;                  // outputs per warp window
constexpr int   kIter  = 32;                   // stored windows per warp segment
constexpr int   kSeg   = kWin * kIter;         // 4096 outputs per warp
constexpr int   kSkip  = 91;
constexpr float C1     = 0.85f;

constexpr float cp(int k) {
    float r = 1.0f;
    for (int i = 0; i < k; ++i) r *= 0.85f;
    return r;
}
constexpr float A1 = cp(1), A2 = cp(2), A3 = cp(3), A4 = cp(4);
constexpr float K1 = cp(4), K2 = cp(8), K3 = cp(16), K4 = cp(32), K5 = cp(64);
}

__device__ __forceinline__ float q16(float v) {
    short q; asm("cvt.rzi.s16.f32 %0, %1;" : "=h"(q) : "f"(v));
    float r; asm("cvt.rn.f32.s16 %0, %1;" : "=f"(r) : "h"(q));
    return r;
}

template <bool EDGE>
__device__ __forceinline__ float4 ld4(const float* __restrict__ x, int e0, int n) {
    if (!EDGE) return *reinterpret_cast<const float4*>(x + e0);
    float4 v;
    v.x = (e0 + 0 >= 0 && e0 + 0 < n) ? x[e0 + 0] : 0.0f;
    v.y = (e0 + 1 >= 0 && e0 + 1 < n) ? x[e0 + 1] : 0.0f;
    v.z = (e0 + 2 >= 0 && e0 + 2 < n) ? x[e0 + 2] : 0.0f;
    v.w = (e0 + 3 >= 0 && e0 + 3 < n) ? x[e0 + 3] : 0.0f;
    return v;
}

struct Win { float y0, y1, y2, y3, P31, Pex; };

// Scan one 128-sample window. cur = this window's float4, nxt = next window's
// (lane0 supplies the realign tail). Returns lane-local partial outputs + scan.
__device__ __forceinline__ Win win_scan(float4 cur, float4 nxt, int l) {
    const unsigned FULL = 0xffffffffu;
    const int src = (l + 1) & 31;
    float tx = (l == 0) ? nxt.x : cur.x;
    float ty = (l == 0) ? nxt.y : cur.y;
    float tz = (l == 0) ? nxt.z : cur.z;
    float ax = __shfl_sync(FULL, tx, src);
    float ay = __shfl_sync(FULL, ty, src);
    float az = __shfl_sync(FULL, tz, src);

    Win w;
    w.y0 = 32768.0f * cur.w;
    w.y1 = fmaf(C1, w.y0, 32768.0f * ax);
    w.y2 = fmaf(C1, w.y1, 32768.0f * ay);
    w.y3 = fmaf(C1, w.y2, 32768.0f * az);

    float P = w.y3, u;
    u = __shfl_up_sync(FULL, P, 1);  P = (l >= 1)  ? fmaf(K1, u, P) : P;
    u = __shfl_up_sync(FULL, P, 2);  P = (l >= 2)  ? fmaf(K2, u, P) : P;
    u = __shfl_up_sync(FULL, P, 4);  P = (l >= 4)  ? fmaf(K3, u, P) : P;
    u = __shfl_up_sync(FULL, P, 8);  P = (l >= 8)  ? fmaf(K4, u, P) : P;
    u = __shfl_up_sync(FULL, P, 16); P = (l >= 16) ? fmaf(K5, u, P) : P;

    float pex = __shfl_up_sync(FULL, P, 1);
    w.Pex = (l == 0) ? 0.0f : pex;
    w.P31 = __shfl_sync(FULL, P, 31);
    return w;
}

__device__ __forceinline__ float4 win_out(const Win& w, float E) {
    float4 o;
    o.x = q16(fmaf(A1, E, w.y0));
    o.y = q16(fmaf(A2, E, w.y1));
    o.z = q16(fmaf(A3, E, w.y2));
    o.w = q16(fmaf(A4, E, w.y3));
    return o;
}

// Fast interior path: dual-window pipelined, unguarded vector I/O.
__device__ __forceinline__ void seg_fast(const float* __restrict__ x,
                                         float* __restrict__ out,
                                         int W0, int l, float c4l)
{
    float4* o4 = reinterpret_cast<float4*>(out);
    // window base address helper: x[W0 + w*128 + 88 + 4l]
    const int base = W0 + 88 + 4 * l;

    float4 m1  = ld4<false>(x, base - kWin, 0);   // window -1 (warmup)
    float4 cur = ld4<false>(x, base, 0);          // window 0
    float4 nx1 = ld4<false>(x, base + kWin, 0);   // window 1

    Win wm = win_scan(m1, cur, l);
    float s = wm.P31;                              // entering state for window 0

    #pragma unroll 2
    for (int w = 0; w < kIter; w += 2) {
        float4 a = ld4<false>(x, base + (w + 2) * kWin, 0);
        float4 bq = ld4<false>(x, base + (w + 3) * kWin, 0);

        Win A = win_scan(cur, nx1, l);             // independent
        Win B = win_scan(nx1, a, l);               // independent

        float EA = fmaf(c4l, s, A.Pex);
        float sA = A.P31;                           // 0.85^128*s ~ 2e-10: dropped
        float EB = fmaf(c4l, sA, B.Pex);
        s = B.P31;

        o4[(W0 + w * kWin) / 4 + l]       = win_out(A, EA);
        o4[(W0 + (w + 1) * kWin) / 4 + l] = win_out(B, EB);

        cur = a; nx1 = bq;
    }
}

// Edge path: scalar per-window loop with full bounds checks.
__device__ __forceinline__ void seg_edge(const float* __restrict__ x,
                                         float* __restrict__ out,
                                         int n, int nout, int W0, int l, float c4l)
{
    const int base = W0 + 88 + 4 * l;
    float s = 0.0f;
    float4 cur = ld4<true>(x, base - kWin, n);
    for (int w = -1; w < kIter; ++w) {
        float4 nxt = ld4<true>(x, base + (w + 1) * kWin, n);
        Win A = win_scan(cur, nxt, l);
        float E = fmaf(c4l, s, A.Pex);
        s = A.P31;
        if (w >= 0) {
            float4 o = win_out(A, E);
            const int oi = W0 + w * kWin + 4 * l;
            const int zf = n - kSkip;
            float v[4] = {o.x, o.y, o.z, o.w};
            #pragma unroll
            for (int e = 0; e < 4; ++e)
                if (oi + e < nout)
                    out[oi + e] = (oi + e < zf) ? v[e] : 0.0f;
        }
        cur = nxt;
    }
}

__global__ __launch_bounds__(kBlock, 4)
void preemph_f32_kernel(const float* __restrict__ x, float* __restrict__ out,
                        int n, int nout)
{
    const int wg = (blockIdx.x * kBlock + threadIdx.x) >> 5;
    const int l  = threadIdx.x & 31;
    const int W0 = wg * kSeg;
    if (W0 >= nout) return;

    float c4l = 1.0f;                    // c^(4l) via bit decomposition
    if (l & 1)  c4l *= K1;
    if (l & 2)  c4l *= K2;
    if (l & 4)  c4l *= K3;
    if (l & 8)  c4l *= K4;
    if (l & 16) c4l *= K5;

    // fast path reads up to window kIter+1 (lookahead) -> margin 512
    const bool edge = (W0 == 0) || (W0 + kSeg + 512 > n) || (W0 + kSeg > nout);
    if (edge) seg_edge(x, out, n, nout, W0, l, c4l);
    else      seg_fast(x, out, W0, l, c4l);
}

extern "C" void kernel_launch(void* const* d_in, const int* in_sizes, int n_in,
                              void* d_out, int out_size) {
    const float* x = (const float*)d_in[0];
    float* out = (float*)d_out;
    const int n = in_sizes[0];
    const int warps = (out_size + kSeg - 1) / kSeg;
    const int grid = (warps + (kBlock / 32) - 1) / (kBlock / 32);
    preemph_f32_kernel<<<grid, kBlock>>>(x, out, n, out_size);
}

// round 10
// speedup vs baseline: 1.0404x; 1.0404x over previous
#include <cuda_runtime.h>
#include <stdint.h>

// Pre-emphasis IIR y[i] = x[i] + 0.85*y[i-1]; out[o] = float(clip_int16(32768*y[o+91])),
// out[N-91..] = 0. Block-parallel via decay (0.85^96 ~ 1.7e-7).
// R10: R6 memory structure (coalesced stage -> padded smem -> conflict-free
// thread-chunk LDS: 96 L1 wf/512 outputs vs R7's 112) + R7 instruction trims
// (q16 cvt quantize, templated fast/edge paths, uniform warmup threads).

namespace {
constexpr int   kBlock = 256;
constexpr int   kChunk = 16;
constexpr int   kWarm  = 6;                     // warmup chunks (96 samples)
constexpr int   kMain  = kBlock - kWarm;        // 250 output chunks
constexpr int   kTile  = kMain * kChunk;        // 4000 outputs per block
constexpr int   kSkip  = 91;
constexpr float C1     = 0.85f;
constexpr int   kWin4  = 1025;                  // staged float4s (4100 floats)
constexpr int   kPadF  = 4100 + (4100 >> 5);    // 4228 padded floats (restage needs 4125)

constexpr float cp(int k) {
    float r = 1.0f;
    for (int i = 0; i < k; ++i) r *= 0.85f;
    return r;
}
constexpr float c16 = cp(16), c32 = cp(32), c48 = cp(48), c64 = cp(64), c80 = cp(80);

struct Pows { float v[17]; };
constexpr Pows mk() {
    Pows p{}; float r = 1.0f;
    for (int i = 0; i < 17; ++i) { p.v[i] = r; r *= 0.85f; }
    return p;
}
__device__ constexpr Pows kP = mk();
}

__device__ __forceinline__ int padf(int l) { return l + (l >> 5); }

// Saturating truncate-toward-zero to int16 range, back to float.
// Matches clip(-32768,32767) + astype(int16) exactly (f32->s16 cvt saturates).
__device__ __forceinline__ float q16(float v) {
    short q; asm("cvt.rzi.s16.f32 %0, %1;" : "=h"(q) : "f"(v));
    float r; asm("cvt.rn.f32.s16 %0, %1;" : "=f"(r) : "h"(q));
    return r;
}

template <bool EDGE>
__global__ __launch_bounds__(kBlock, 8)
void preemph_f32_kernel(const float* __restrict__ x, float* __restrict__ out,
                        int n, int nout)
{
    __shared__ float sm[kPadF];                  // input window, reused for outputs
    __shared__ float sB[kBlock];                 // chunk end-states
    const int b = EDGE ? (blockIdx.x == 0 ? 0 : blockIdx.x + (nout / kTile - 2))
                       : blockIdx.x + 1;         // edge grid covers {0, tail...}
    const int t = threadIdx.x;
    const int O = b * kTile;                     // first output of this block
    // thread t scans x[S_t..S_t+16), S_t = O + 16t - 5 (thread 6 -> y at O+91).
    // window base Fa = O - 8 (float4-aligned); logical offset of S_t = 16t + 3.
    const int Fa = O - 8;

    // ---- Stage window: coalesced LDG.128 -> padded scalar STS ----
    for (int i = t; i < kWin4; i += kBlock) {
        const int g = Fa + 4 * i;
        float4 u;
        if (!EDGE) {
            u = *reinterpret_cast<const float4*>(x + g);
        } else {
            u.x = (g + 0 >= 0 && g + 0 < n) ? x[g + 0] : 0.0f;
            u.y = (g + 1 >= 0 && g + 1 < n) ? x[g + 1] : 0.0f;
            u.z = (g + 2 >= 0 && g + 2 < n) ? x[g + 2] : 0.0f;
            u.w = (g + 3 >= 0 && g + 3 < n) ? x[g + 3] : 0.0f;
        }
        const int p = 4 * i + (i >> 3);          // == padf(4*i); 4 floats contiguous
        sm[p]     = u.x;
        sm[p + 1] = u.y;
        sm[p + 2] = u.z;
        sm[p + 3] = u.w;
    }
    __syncthreads();

    // ---- Per-thread local scan (zero entry state); conflict-free stride-17 banks ----
    const int lb = 16 * t + 3;
    float res[kChunk];
    float y = 0.0f;
    #pragma unroll
    for (int k = 0; k < kChunk; ++k) {
        y = fmaf(C1, y, sm[padf(lb + k)]);
        res[k] = y;
    }
    sB[t] = y;
    __syncthreads();                             // sB ready; all sm reads done

    // ---- Depth-6 carry, correct, quantize, restage (reuse sm) ----
    if (t >= kWarm) {
        float s = sB[t - 1];
        s = fmaf(c16, sB[t - 2], s);
        s = fmaf(c32, sB[t - 3], s);
        s = fmaf(c48, sB[t - 4], s);
        s = fmaf(c64, sB[t - 5], s);
        s = fmaf(c80, sB[t - 6], s);
        const int base = 16 * (t - kWarm);       // block-local output position
        #pragma unroll
        for (int k = 0; k < kChunk; ++k)
            sm[padf(base + k)] = q16(32768.0f * fmaf(s, kP.v[k + 1], res[k]));
    }
    __syncthreads();

    // ---- Coalesced stores ----
    if (!EDGE) {
        float4* o4 = reinterpret_cast<float4*>(out + O);
        #pragma unroll
        for (int m = 0; m < 4; ++m) {
            const int j = t + m * kBlock;
            if (j < kTile / 4) {                 // 1000 float4s
                const int p = padf(4 * j);       // group of 4 contiguous
                float4 u;
                u.x = sm[p]; u.y = sm[p + 1]; u.z = sm[p + 2]; u.w = sm[p + 3];
                o4[j] = u;
            }
        }
    } else {
        const int rem = min(kTile, nout - O);
        const int zf  = (n - kSkip) - O;         // outputs at/after this are 0
        for (int i = t; i < rem; i += kBlock)
            out[O + i] = (i < zf) ? sm[padf(i)] : 0.0f;
    }
}

extern "C" void kernel_launch(void* const* d_in, const int* in_sizes, int n_in,
                              void* d_out, int out_size) {
    const float* x = (const float*)d_in[0];
    float* out = (float*)d_out;
    const int n = in_sizes[0];
    const int nblk = (out_size + kTile - 1) / kTile;
    // Interior blocks b=1..nblk-3 are guaranteed fast (window+tile fully in range,
    // before the zero tail); blocks {0, nblk-2, nblk-1} take the edge path.
    const int nfast = nblk > 3 ? nblk - 3 : 0;
    const int nedge = nblk - nfast;
    if (nfast > 0)
        preemph_f32_kernel<false><<<nfast, kBlock>>>(x, out, n, out_size);
    preemph_f32_kernel<true><<<nedge, kBlock>>>(x, out, n, out_size);
}

// round 11
// speedup vs baseline: 1.0874x; 1.0451x over previous
#include <cuda_runtime.h>
#include <stdint.h>

// Pre-emphasis IIR y[i] = x[i] + 0.85*y[i-1]; out[o] = float(clip_int16(32768*y[o+91])),
// out[N-91..] = 0.
// R11: R8's register-only warp-scan math (coalesced float4 I/O, shuffle realign,
// Kogge-Stone weighted scan) with R7's parallel structure: ONE window per warp,
// 9 warps/block (1 warmup + 8 output windows), inter-window carry E_{j+1}=P31_j
// exchanged through smem after one barrier (c^128 ~ 2e-10 -> zero-entry scans
// exact). No serial window chain, no smem transpose: ~36 L1 wf / 512 outputs.

namespace {
constexpr int   kWarps   = 9;
constexpr int   kWMain   = 8;
constexpr int   kThreads = kWarps * 32;        // 288
constexpr int   kWin     = 128;                // outputs per warp window
constexpr int   kTile    = kWMain * kWin;      // 1024 outputs per block
constexpr int   kSkip    = 91;
constexpr float C1       = 0.85f;

constexpr float cp(int k) {
    float r = 1.0f;
    for (int i = 0; i < k; ++i) r *= 0.85f;
    return r;
}
constexpr float A1 = cp(1), A2 = cp(2), A3 = cp(3), A4 = cp(4);
constexpr float K1 = cp(4), K2 = cp(8), K3 = cp(16), K4 = cp(32), K5 = cp(64);
}

// Saturating truncate-toward-zero to int16 range, back to float.
// Matches clip(-32768,32767) + astype(int16) exactly (f32->s16 cvt saturates).
__device__ __forceinline__ float q16(float v) {
    short q; asm("cvt.rzi.s16.f32 %0, %1;" : "=h"(q) : "f"(v));
    float r; asm("cvt.rn.f32.s16 %0, %1;" : "=f"(r) : "h"(q));
    return r;
}

template <bool EDGE>
__device__ __forceinline__ float4 ld4(const float* __restrict__ x, int e0, int n) {
    if (!EDGE) return *reinterpret_cast<const float4*>(x + e0);
    float4 v;
    v.x = (e0 + 0 >= 0 && e0 + 0 < n) ? x[e0 + 0] : 0.0f;
    v.y = (e0 + 1 >= 0 && e0 + 1 < n) ? x[e0 + 1] : 0.0f;
    v.z = (e0 + 2 >= 0 && e0 + 2 < n) ? x[e0 + 2] : 0.0f;
    v.w = (e0 + 3 >= 0 && e0 + 3 < n) ? x[e0 + 3] : 0.0f;
    return v;
}

template <bool EDGE>
__device__ __forceinline__ void block_body(const float* __restrict__ x,
                                           float* __restrict__ out,
                                           int n, int nout, int O, int w, int l)
{
    __shared__ float4 sTail[kWarps];   // lane-0 float4 of each warp's window
    __shared__ float  sP[kWarps];      // zero-entry end state of each window
    const unsigned FULL = 0xffffffffu;

    // warp w scans window j = w-1 (w=0: warmup). Load covers window-local
    // elements [88+4l, 92+4l): y sample for output O+128j+4l+k is at +91+4l+k.
    const int e0 = O + kWin * w - 40 + 4 * l;
    float4 cur = ld4<EDGE>(x, e0, n);
    if (l == 0) sTail[w] = cur;

    // last warp's lane 31 realign tail comes from beyond the block's windows
    float4 ext;
    if (w == kWarps - 1 && l == 31)
        ext = ld4<EDGE>(x, O + kWin * kWarps - 40, n);

    // c^(4l) via bit decomposition
    float c4l = 1.0f;
    if (l & 1)  c4l *= K1;
    if (l & 2)  c4l *= K2;
    if (l & 4)  c4l *= K3;
    if (l & 8)  c4l *= K4;
    if (l & 16) c4l *= K5;

    __syncthreads();                   // sTail visible

    // realign +3: lane l's samples = {cur.w, lane(l+1).{x,y,z}}
    float ax = __shfl_down_sync(FULL, cur.x, 1);
    float ay = __shfl_down_sync(FULL, cur.y, 1);
    float az = __shfl_down_sync(FULL, cur.z, 1);
    if (l == 31) {
        float4 t = (w == kWarps - 1) ? ext : sTail[w + 1];
        ax = t.x; ay = t.y; az = t.z;
    }

    // lane-local 4-sample scan from zero state (pre-scaled by 32768)
    float y0 = 32768.0f * cur.w;
    float y1 = fmaf(C1, y0, 32768.0f * ax);
    float y2 = fmaf(C1, y1, 32768.0f * ay);
    float y3 = fmaf(C1, y2, 32768.0f * az);

    // Kogge-Stone weighted inclusive scan of lane end-states
    float P = y3, u;
    u = __shfl_up_sync(FULL, P, 1);  P = (l >= 1)  ? fmaf(K1, u, P) : P;
    u = __shfl_up_sync(FULL, P, 2);  P = (l >= 2)  ? fmaf(K2, u, P) : P;
    u = __shfl_up_sync(FULL, P, 4);  P = (l >= 4)  ? fmaf(K3, u, P) : P;
    u = __shfl_up_sync(FULL, P, 8);  P = (l >= 8)  ? fmaf(K4, u, P) : P;
    u = __shfl_up_sync(FULL, P, 16); P = (l >= 16) ? fmaf(K5, u, P) : P;

    float pex = __shfl_up_sync(FULL, P, 1);
    if (l == 0) pex = 0.0f;
    float P31 = __shfl_sync(FULL, P, 31);
    if (l == 0) sP[w] = P31;
    __syncthreads();                   // sP visible

    if (w > 0) {
        // window entering state = previous window's zero-entry end state
        // (dropped c^128 * E_prev term ~ 2e-10: windows decouple)
        float Ew = sP[w - 1];
        float E  = fmaf(c4l, Ew, pex);
        float4 o;
        o.x = q16(fmaf(A1, E, y0));
        o.y = q16(fmaf(A2, E, y1));
        o.z = q16(fmaf(A3, E, y2));
        o.w = q16(fmaf(A4, E, y3));
        const int ob = O + (w - 1) * kWin;     // window output base
        if (!EDGE) {
            reinterpret_cast<float4*>(out)[(ob >> 2) + l] = o;
        } else {
            const int oi = ob + 4 * l;
            const int zf = n - kSkip;          // outputs at/after this are 0
            float v[4] = {o.x, o.y, o.z, o.w};
            #pragma unroll
            for (int e = 0; e < 4; ++e)
                if (oi + e < nout)
                    out[oi + e] = (oi + e < zf) ? v[e] : 0.0f;
        }
    }
}

__global__ __launch_bounds__(kThreads)
void preemph_f32_kernel(const float* __restrict__ x, float* __restrict__ out,
                        int n, int nout)
{
    const int b = blockIdx.x;
    const int w = threadIdx.x >> 5;
    const int l = threadIdx.x & 31;
    const int O = b * kTile;
    // interior needs loads up to O + 9*128 - 40 + 3 = O + kTile + 115 < n,
    // warmup loads >= O - 40 >= 0, and the whole tile before the zero tail.
    const bool edge = (b == 0) || (O + kTile + 116 > n) || (O + kTile > nout)
                   || (O + kTile > n - kSkip);
    if (edge) block_body<true >(x, out, n, nout, O, w, l);
    else      block_body<false>(x, out, n, nout, O, w, l);
}

extern "C" void kernel_launch(void* const* d_in, const int* in_sizes, int n_in,
                              void* d_out, int out_size) {
    const float* x = (const float*)d_in[0];
    float* out = (float*)d_out;
    const int n = in_sizes[0];
    const int grid = (out_size + kTile - 1) / kTile;
    preemph_f32_kernel<<<grid, kThreads>>>(x, out, n, out_size);
}

// round 12
// speedup vs baseline: 1.3431x; 1.2352x over previous
#include <cuda_runtime.h>
#include <stdint.h>

// Pre-emphasis IIR y[i] = x[i] + 0.85*y[i-1]; out[o] = float(clip_int16(32768*y[o+91])),
// out[N-91..] = 0.
// R12: warp Kogge-Stone scan, 4 windows per warp. Windows decouple because the
// entering state of window j is the zero-entry P31 of window j-1 (c^128 ~ 2e-10).
// 8 warps scan 32 windows (1 warmup + 31 output); one float/warp through smem,
// one barrier. 4 up-front LDG.128 per lane -> MLP 4 to feed DRAM; all I/O coalesced.

namespace {
constexpr int   kWarps   = 8;
constexpr int   kThreads = kWarps * 32;          // 256
constexpr int   kWpw     = 4;                    // windows per warp
constexpr int   kWin     = 128;                  // outputs per window
constexpr int   kTile    = (kWarps * kWpw - 1) * kWin;  // 31 windows = 3968
constexpr int   kSkip    = 91;
constexpr float C1       = 0.85f;

constexpr float cp(int k) {
    float r = 1.0f;
    for (int i = 0; i < k; ++i) r *= 0.85f;
    return r;
}
constexpr float A1 = cp(1), A2 = cp(2), A3 = cp(3), A4 = cp(4);
constexpr float K1 = cp(4), K2 = cp(8), K3 = cp(16), K4 = cp(32), K5 = cp(64);
}

// Saturating truncate-toward-zero to int16 range, back to float.
// Matches clip(-32768,32767) + astype(int16) exactly (f32->s16 cvt saturates).
__device__ __forceinline__ float q16(float v) {
    short q; asm("cvt.rzi.s16.f32 %0, %1;" : "=h"(q) : "f"(v));
    float r; asm("cvt.rn.f32.s16 %0, %1;" : "=f"(r) : "h"(q));
    return r;
}

template <bool EDGE>
__device__ __forceinline__ float4 ld4(const float* __restrict__ x, int e0, int n) {
    if (!EDGE) return *reinterpret_cast<const float4*>(x + e0);
    float4 v;
    v.x = (e0 + 0 >= 0 && e0 + 0 < n) ? x[e0 + 0] : 0.0f;
    v.y = (e0 + 1 >= 0 && e0 + 1 < n) ? x[e0 + 1] : 0.0f;
    v.z = (e0 + 2 >= 0 && e0 + 2 < n) ? x[e0 + 2] : 0.0f;
    v.w = (e0 + 3 >= 0 && e0 + 3 < n) ? x[e0 + 3] : 0.0f;
    return v;
}

template <bool EDGE>
__device__ __forceinline__ void block_body(const float* __restrict__ x,
                                           float* __restrict__ out,
                                           int n, int nout, int O, int w, int l)
{
    __shared__ float sLast[kWarps];    // each warp's last-window zero-entry P31
    const unsigned FULL = 0xffffffffu;

    // warp w scans block windows j = 4w-1+i, i=0..3 (j=-1 is the warmup).
    // Window j's lane-l load: x[O + 128j + 88 + 4l .. +4).
    const int eb = O + kWin * (kWpw * w - 1) + 88 + 4 * l;
    float4 cur[kWpw];
    #pragma unroll
    for (int i = 0; i < kWpw; ++i)
        cur[i] = ld4<EDGE>(x, eb + i * kWin, n);
    // lane 31's realign tail for the last window (start of window 4w+3)
    float4 ext;
    if (l == 31)
        ext = ld4<EDGE>(x, O + kWin * (kWpw * w + kWpw - 1) + 88, n);

    // c^(4l) via bit decomposition
    float c4l = 1.0f;
    if (l & 1)  c4l *= K1;
    if (l & 2)  c4l *= K2;
    if (l & 4)  c4l *= K3;
    if (l & 8)  c4l *= K4;
    if (l & 16) c4l *= K5;

    float y0[kWpw], y1[kWpw], y2[kWpw], y3[kWpw], P31[kWpw], pex[kWpw];

    #pragma unroll
    for (int i = 0; i < kWpw; ++i) {
        // realign +3: lane l's samples = {cur.w, lane(l+1).{x,y,z}};
        // lane 31 takes window i+1's lane-0 float4 (same warp) or ext.
        float ax = __shfl_down_sync(FULL, cur[i].x, 1);
        float ay = __shfl_down_sync(FULL, cur[i].y, 1);
        float az = __shfl_down_sync(FULL, cur[i].z, 1);
        float bx, by, bz;
        if (i < kWpw - 1) {
            bx = __shfl_sync(FULL, cur[i + 1].x, 0);
            by = __shfl_sync(FULL, cur[i + 1].y, 0);
            bz = __shfl_sync(FULL, cur[i + 1].z, 0);
        } else {
            bx = ext.x; by = ext.y; bz = ext.z;    // only lane 31 uses these
        }
        if (l == 31) { ax = bx; ay = by; az = bz; }

        // lane-local 4-sample scan from zero state (pre-scaled by 32768)
        float a0 = 32768.0f * cur[i].w;
        float a1 = fmaf(C1, a0, 32768.0f * ax);
        float a2 = fmaf(C1, a1, 32768.0f * ay);
        float a3 = fmaf(C1, a2, 32768.0f * az);
        y0[i] = a0; y1[i] = a1; y2[i] = a2; y3[i] = a3;

        // Kogge-Stone weighted inclusive scan of lane end-states
        float P = a3, u;
        u = __shfl_up_sync(FULL, P, 1);  P = (l >= 1)  ? fmaf(K1, u, P) : P;
        u = __shfl_up_sync(FULL, P, 2);  P = (l >= 2)  ? fmaf(K2, u, P) : P;
        u = __shfl_up_sync(FULL, P, 4);  P = (l >= 4)  ? fmaf(K3, u, P) : P;
        u = __shfl_up_sync(FULL, P, 8);  P = (l >= 8)  ? fmaf(K4, u, P) : P;
        u = __shfl_up_sync(FULL, P, 16); P = (l >= 16) ? fmaf(K5, u, P) : P;

        float pe = __shfl_up_sync(FULL, P, 1);
        pex[i] = (l == 0) ? 0.0f : pe;
        P31[i] = __shfl_sync(FULL, P, 31);
    }

    if (l == 0) sLast[w] = P31[kWpw - 1];
    __syncthreads();

    // Entering state of first window: previous warp's last window P31
    // (warp 0's first window is the warmup; its entering state only matters
    //  through c^128 -> 0 is exact enough).
    float S = (w == 0) ? 0.0f : sLast[w - 1];

    #pragma unroll
    for (int i = 0; i < kWpw; ++i) {
        float E = fmaf(c4l, S, pex[i]);
        S = P31[i];                                // carry to next window
        const int j = kWpw * w - 1 + i;            // block window index
        if (j < 0) continue;                       // warmup: no store
        float4 o;
        o.x = q16(fmaf(A1, E, y0[i]));
        o.y = q16(fmaf(A2, E, y1[i]));
        o.z = q16(fmaf(A3, E, y2[i]));
        o.w = q16(fmaf(A4, E, y3[i]));
        const int ob = O + j * kWin;
        if (!EDGE) {
            reinterpret_cast<float4*>(out)[(ob >> 2) + l] = o;
        } else {
            const int oi = ob + 4 * l;
            const int zf = n - kSkip;              // outputs at/after this are 0
            float v[4] = {o.x, o.y, o.z, o.w};
            #pragma unroll
            for (int e = 0; e < 4; ++e)
                if (oi + e < nout)
                    out[oi + e] = (oi + e < zf) ? v[e] : 0.0f;
        }
    }
}

__global__ __launch_bounds__(kThreads, 5)
void preemph_f32_kernel(const float* __restrict__ x, float* __restrict__ out,
                        int n, int nout)
{
    const int b = blockIdx.x;
    const int w = threadIdx.x >> 5;
    const int l = threadIdx.x & 31;
    const int O = b * kTile;
    if (O >= nout) return;
    // interior: min load O-40 >= 0 (b>=1); max load O + 128*31 + 88 + 3 = O+4059;
    // all outputs before zero tail and inside nout.
    const bool edge = (b == 0) || (O + kTile + 128 > n) || (O + kTile > nout)
                   || (O + kTile > n - kSkip);
    if (edge) block_body<true >(x, out, n, nout, O, w, l);
    else      block_body<false>(x, out, n, nout, O, w, l);
}

extern "C" void kernel_launch(void* const* d_in, const int* in_sizes, int n_in,
                              void* d_out, int out_size) {
    const float* x = (const float*)d_in[0];
    float* out = (float*)d_out;
    const int n = in_sizes[0];
    const int grid = (out_size + kTile - 1) / kTile;
    preemph_f32_kernel<<<grid, kThreads>>>(x, out, n, out_size);
}

// round 13
// speedup vs baseline: 1.3816x; 1.0287x over previous
#include <cuda_runtime.h>
#include <stdint.h>

// Pre-emphasis IIR y[i] = x[i] + 0.85*y[i-1]; out[o] = float(clip_int16(32768*y[o+91])),
// out[N-91..] = 0.
// R13: R12's warp Kogge-Stone with 8 samples/lane (256-output windows): shuffles
// per 512 outputs drop 52 -> 18 (3 realign + 4 KS levels + pex + P31 per window;
// the c^128 KS level is dropped, contribution ~9e-10). 2 windows/warp, 8 warps,
// tile 3840 (1 warmup window), one float/warp through smem, one barrier.

namespace {
constexpr int   kWarps   = 8;
constexpr int   kThreads = kWarps * 32;          // 256
constexpr int   kWin     = 256;                  // outputs per window (8/lane)
constexpr int   kWinTot  = 2 * kWarps;           // 16 windows incl. warmup
constexpr int   kTile    = (kWinTot - 1) * kWin; // 3840 outputs per block
constexpr int   kSkip    = 91;
constexpr float C1       = 0.85f;

constexpr float cp(int k) {
    float r = 1.0f;
    for (int i = 0; i < k; ++i) r *= 0.85f;
    return r;
}
// correction coefficients for sample k in lane chunk: true y_k = y_k + E*c^(k+1)
constexpr float A1 = cp(1), A2 = cp(2), A3 = cp(3), A4 = cp(4);
constexpr float A5 = cp(5), A6 = cp(6), A7 = cp(7), A8 = cp(8);
// Kogge-Stone merge weights (8 samples/lane)
constexpr float W1 = cp(8), W2 = cp(16), W3 = cp(32), W4 = cp(64), W5 = cp(128);
}

// Saturating truncate-toward-zero to int16 range, back to float.
// Matches clip(-32768,32767) + astype(int16) exactly (f32->s16 cvt saturates).
__device__ __forceinline__ float q16(float v) {
    short q; asm("cvt.rzi.s16.f32 %0, %1;" : "=h"(q) : "f"(v));
    float r; asm("cvt.rn.f32.s16 %0, %1;" : "=f"(r) : "h"(q));
    return r;
}

template <bool EDGE>
__device__ __forceinline__ float4 ld4(const float* __restrict__ x, int e0, int n) {
    if (!EDGE) return *reinterpret_cast<const float4*>(x + e0);
    float4 v;
    v.x = (e0 + 0 >= 0 && e0 + 0 < n) ? x[e0 + 0] : 0.0f;
    v.y = (e0 + 1 >= 0 && e0 + 1 < n) ? x[e0 + 1] : 0.0f;
    v.z = (e0 + 2 >= 0 && e0 + 2 < n) ? x[e0 + 2] : 0.0f;
    v.w = (e0 + 3 >= 0 && e0 + 3 < n) ? x[e0 + 3] : 0.0f;
    return v;
}

// 4-level weighted Kogge-Stone (c^128 level dropped; error < 1e-9 relative)
__device__ __forceinline__ void ks4(float yEnd, int l, float& pex, float& P31) {
    const unsigned FULL = 0xffffffffu;
    float P = yEnd, u;
    u = __shfl_up_sync(FULL, P, 1); P = (l >= 1) ? fmaf(W1, u, P) : P;
    u = __shfl_up_sync(FULL, P, 2); P = (l >= 2) ? fmaf(W2, u, P) : P;
    u = __shfl_up_sync(FULL, P, 4); P = (l >= 4) ? fmaf(W3, u, P) : P;
    u = __shfl_up_sync(FULL, P, 8); P = (l >= 8) ? fmaf(W4, u, P) : P;
    float pe = __shfl_up_sync(FULL, P, 1);
    pex = (l == 0) ? 0.0f : pe;
    P31 = __shfl_sync(FULL, P, 31);
}

__device__ __forceinline__ void scan8(const float4& u, const float4& v,
                                      float nx, float ny, float nz, float* y) {
    // lane samples (post +3 realign): {u.w, v.x, v.y, v.z, v.w, nx, ny, nz}
    y[0] = u.w;
    y[1] = fmaf(C1, y[0], v.x);
    y[2] = fmaf(C1, y[1], v.y);
    y[3] = fmaf(C1, y[2], v.z);
    y[4] = fmaf(C1, y[3], v.w);
    y[5] = fmaf(C1, y[4], nx);
    y[6] = fmaf(C1, y[5], ny);
    y[7] = fmaf(C1, y[6], nz);
}

template <bool EDGE>
__device__ __forceinline__ void emit(float* __restrict__ out, const float* y,
                                     float E, int ob, int l, int n, int nout) {
    float o0 = q16(32768.0f * fmaf(A1, E, y[0]));
    float o1 = q16(32768.0f * fmaf(A2, E, y[1]));
    float o2 = q16(32768.0f * fmaf(A3, E, y[2]));
    float o3 = q16(32768.0f * fmaf(A4, E, y[3]));
    float o4 = q16(32768.0f * fmaf(A5, E, y[4]));
    float o5 = q16(32768.0f * fmaf(A6, E, y[5]));
    float o6 = q16(32768.0f * fmaf(A7, E, y[6]));
    float o7 = q16(32768.0f * fmaf(A8, E, y[7]));
    if (!EDGE) {
        float4* o4p = reinterpret_cast<float4*>(out);
        const int idx = (ob >> 2) + 2 * l;
        o4p[idx]     = make_float4(o0, o1, o2, o3);
        o4p[idx + 1] = make_float4(o4, o5, o6, o7);
    } else {
        const int oi = ob + 8 * l;
        const int zf = n - kSkip;                // outputs at/after this are 0
        float v[8] = {o0, o1, o2, o3, o4, o5, o6, o7};
        #pragma unroll
        for (int e = 0; e < 8; ++e)
            if (oi + e < nout)
                out[oi + e] = (oi + e < zf) ? v[e] : 0.0f;
    }
}

template <bool EDGE>
__device__ __forceinline__ void block_body(const float* __restrict__ x,
                                           float* __restrict__ out,
                                           int n, int nout, int O, int w, int l)
{
    __shared__ float sLast[kWarps];
    const unsigned FULL = 0xffffffffu;

    // warp w owns windows jA = 2w-1 (w=0: warmup, unstored) and jB = 2w.
    // Window j lane-l loads: x[O + 256j + 88 + 8l .. +8)
    const int baseA = O + kWin * (2 * w - 1) + 88 + 8 * l;
    float4 uA = ld4<EDGE>(x, baseA, n);
    float4 vA = ld4<EDGE>(x, baseA + 4, n);
    float4 uB = ld4<EDGE>(x, baseA + kWin, n);
    float4 vB = ld4<EDGE>(x, baseA + kWin + 4, n);
    float ex = 0.0f, ey = 0.0f, ez = 0.0f;       // window B realign tail (lane 31)
    if (l == 31) {
        float4 e = ld4<EDGE>(x, O + kWin * (2 * w + 1) + 88, n);
        ex = e.x; ey = e.y; ez = e.z;
    }

    // c^(8l) via bit decomposition (W5 term required for correctness of high lanes)
    float c8l = 1.0f;
    if (l & 1)  c8l *= W1;
    if (l & 2)  c8l *= W2;
    if (l & 4)  c8l *= W3;
    if (l & 8)  c8l *= W4;
    if (l & 16) c8l *= W5;

    // window A realign: next lane's u.{x,y,z}; lane 31 needs window B's lane-0 u,
    // supplied by pre-selecting on lane 0 then shuffling from lane (l+1)&31.
    const int src = (l + 1) & 31;
    float tx = (l == 0) ? uB.x : uA.x;
    float ty = (l == 0) ? uB.y : uA.y;
    float tz = (l == 0) ? uB.z : uA.z;
    float nax = __shfl_sync(FULL, tx, src);
    float nay = __shfl_sync(FULL, ty, src);
    float naz = __shfl_sync(FULL, tz, src);

    float yA[8];
    scan8(uA, vA, nax, nay, naz, yA);
    float peA, PA;
    ks4(yA[7], l, peA, PA);

    // window B realign: shfl_down; lane 31 overrides with its own ext load
    float nbx = __shfl_down_sync(FULL, uB.x, 1);
    float nby = __shfl_down_sync(FULL, uB.y, 1);
    float nbz = __shfl_down_sync(FULL, uB.z, 1);
    if (l == 31) { nbx = ex; nby = ey; nbz = ez; }

    float yB[8];
    scan8(uB, vB, nbx, nby, nbz, yB);
    float peB, PB;
    ks4(yB[7], l, peB, PB);

    if (l == 0) sLast[w] = PB;
    __syncthreads();

    // entering state of window jA = P31 of window jA-1 (c^256 term dropped)
    const float S = (w == 0) ? 0.0f : sLast[w - 1];

    if (w > 0)                                    // window A (skip warmup)
        emit<EDGE>(out, yA, fmaf(c8l, S, peA), O + (2 * w - 1) * kWin, l, n, nout);
    // window B: entering state = PA
    emit<EDGE>(out, yB, fmaf(c8l, PA, peB), O + 2 * w * kWin, l, n, nout);
}

__global__ __launch_bounds__(kThreads, 5)
void preemph_f32_kernel(const float* __restrict__ x, float* __restrict__ out,
                        int n, int nout)
{
    const int b = blockIdx.x;
    const int w = threadIdx.x >> 5;
    const int l = threadIdx.x & 31;
    const int O = b * kTile;
    if (O >= nout) return;
    // interior: min load O-168 >= 0 (b>=1); max load O+3931 (< O+kTile+92);
    // tile entirely before nout and the zero tail.
    const bool edge = (b == 0) || (O + kTile + 92 > n) || (O + kTile > nout)
                   || (O + kTile > n - kSkip);
    if (edge) block_body<true >(x, out, n, nout, O, w, l);
    else      block_body<false>(x, out, n, nout, O, w, l);
}

extern "C" void kernel_launch(void* const* d_in, const int* in_sizes, int n_in,
                              void* d_out, int out_size) {
    const float* x = (const float*)d_in[0];
    float* out = (float*)d_out;
    const int n = in_sizes[0];
    const int grid = (out_size + kTile - 1) / kTile;
    preemph_f32_kernel<<<grid, kThreads>>>(x, out, n, out_size);
}